// round 9
// baseline (speedup 1.0000x reference)
#include <cuda_runtime.h>
#include <math.h>
#include <stdint.h>

#define N_SEQ   2048
#define SEQ_LEN 24
#define SEQ_C   9
#define N_FILT  32
#define KM      16
#define HID     128
#define NCLS    10

#define KSTRIDE 145   // padded floats per filter: 145 mod 32 = 17, gcd(17,32)=1 -> conflict-free

__device__ float g_feats[N_SEQ * N_FILT];

__device__ __forceinline__ void cp_async16(uint32_t saddr, const void* gptr) {
    asm volatile("cp.async.cg.shared.global [%0], [%1], 16;" :: "r"(saddr), "l"(gptr));
}
__device__ __forceinline__ void cp_async_commit() {
    asm volatile("cp.async.commit_group;");
}

// ---------------------------------------------------------------------------
// DTW: 64 threads = 2 warps = 2 sequences per block; lane = filter.
// Kernel tensor (18KB) staged raw (no transpose) into padded smem with fully
// coalesced float4 loads; inner-loop reads kS[f*145 + i*9 + c] are
// bank-conflict-free. Row norms computed from registers. Inner DP loop is the
// r2-proven scalar code. Forward DP == backtracked path-cost sum (exact).
// ---------------------------------------------------------------------------
__global__ __launch_bounds__(64) void dtw_kernel(const float* __restrict__ x,
                                                 const float* __restrict__ kernels) {
    __shared__ float kS[N_FILT * KSTRIDE];     // 18.56KB, layout [f][i*9+c] padded
    __shared__ float seqS[2][SEQ_LEN * SEQ_C];
    __shared__ float snS[2][SEQ_LEN];

    const int t   = threadIdx.x;
    const int wid = t >> 5;
    const int f   = t & 31;
    const int s   = blockIdx.x * 2 + wid;

    // Stage kernels: 1152 float4, coalesced. 36 float4 per filter (no straddle).
    {
        const float4* g4 = reinterpret_cast<const float4*>(kernels);
        for (int i4 = t; i4 < N_FILT * 36; i4 += 64) {
            float4 v = g4[i4];
            int ff = i4 / 36;
            int r4 = i4 - ff * 36;
            float* dst = &kS[ff * KSTRIDE + r4 * 4];
            dst[0] = v.x; dst[1] = v.y; dst[2] = v.z; dst[3] = v.w;
        }
    }
    // Stage this warp's sequence (216 contiguous floats)
    {
        const float* xs = x + s * (SEQ_LEN * SEQ_C);
        for (int i = f; i < SEQ_LEN * SEQ_C; i += 32) seqS[wid][i] = xs[i];
    }
    __syncthreads();

    // Sequence-column norms (per warp)
    if (f < SEQ_LEN) {
        float a = 0.f;
#pragma unroll
        for (int c = 0; c < SEQ_C; ++c) {
            float v = seqS[wid][f * SEQ_C + c];
            a = fmaf(v, v, a);
        }
        snS[wid][f] = a;
    }
    __syncwarp();

    const float* kf = &kS[f * KSTRIDE];
    float Dp[SEQ_LEN];

    // ---- Row 0: cumulative sum of C[0][j] ----
    {
        float k0[SEQ_C];
        float kn = 0.f;
#pragma unroll
        for (int c = 0; c < SEQ_C; ++c) {
            k0[c] = kf[c];
            kn = fmaf(k0[c], k0[c], kn);
        }
        float run = 0.f;
#pragma unroll
        for (int j = 0; j < SEQ_LEN; ++j) {
            float dot = 0.f;
#pragma unroll
            for (int c = 0; c < SEQ_C; ++c) dot = fmaf(k0[c], seqS[wid][j * SEQ_C + c], dot);
            float Cv = fmaf(-2.f, dot, kn + snS[wid][j]);
            run = (j == 0) ? Cv : (run + Cv);
            Dp[j] = run;
        }
    }

    const float INF = __int_as_float(0x7f800000);

    // ---- Rows 1..15 in 3 sweeps of 5 ----
    for (int sw = 0; sw < 3; ++sw) {
        const int i0 = 1 + sw * 5;
        float kr[5][SEQ_C], knr[5], left[5];
#pragma unroll
        for (int r = 0; r < 5; ++r) {
            float kn = 0.f;
#pragma unroll
            for (int c = 0; c < SEQ_C; ++c) {
                kr[r][c] = kf[(i0 + r) * SEQ_C + c];
                kn = fmaf(kr[r][c], kr[r][c], kn);
            }
            knr[r] = kn;
            left[r] = INF;
        }
        float diagc = INF;
#pragma unroll
        for (int j = 0; j < SEQ_LEN; ++j) {
            float sv[SEQ_C];
#pragma unroll
            for (int c = 0; c < SEQ_C; ++c) sv[c] = seqS[wid][j * SEQ_C + c];
            float sn = snS[wid][j];
            float up = Dp[j];
            float oldup = up;
            float diag = diagc;
#pragma unroll
            for (int r = 0; r < 5; ++r) {
                float dot = 0.f;
#pragma unroll
                for (int c = 0; c < SEQ_C; ++c) dot = fmaf(kr[r][c], sv[c], dot);
                float Cv = fmaf(-2.f, dot, knr[r] + sn);
                float best = fminf(left[r], fminf(up, diag));
                float d = Cv + best;
                diag = left[r];
                left[r] = d;
                up = d;
            }
            Dp[j] = up;
            diagc = oldup;
        }
    }

    g_feats[s * N_FILT + f] = Dp[SEQ_LEN - 1];
}

// ---------------------------------------------------------------------------
// MLP: 256 threads, 8 seqs/block. W2 cp.async'd in TWO commit groups so
// layer 2's lower half starts while the upper half is still in flight.
// Wl staged transposed. (r6-proven structure.)
// ---------------------------------------------------------------------------
__global__ __launch_bounds__(256) void mlp_kernel(
    const float* __restrict__ W1, const float* __restrict__ b1,
    const float* __restrict__ W2, const float* __restrict__ b2,
    const float* __restrict__ Wl, const float* __restrict__ bl,
    float* __restrict__ out) {
    extern __shared__ float smem[];
    float* W2s = smem;                       // [HID*HID]           64KB
    float* t1S = W2s + HID * HID;            // [h][8 seqs]          4KB
    float* t2S = t1S + HID * 8;              // [h][8 seqs]          4KB
    float* fSt = t2S + HID * 8;              // [filter][8 seqs]     1KB
    float* WlS = fSt + N_FILT * 8;           // [c][h] transposed    5KB

    const int t    = threadIdx.x;
    const int hu   = t & 127;
    const int half = t >> 7;
    const int s0   = blockIdx.x * 8;

    // Prefetch W2: group 0 = rows 0..63 (lower 32KB), group 1 = rows 64..127.
    {
        uint32_t base = (uint32_t)__cvta_generic_to_shared(W2s);
        const float4* g = reinterpret_cast<const float4*>(W2);
#pragma unroll
        for (int i = 0; i < 8; ++i) {
            int e = t + i * 256;
            cp_async16(base + e * 16, g + e);
        }
        cp_async_commit();
#pragma unroll
        for (int i = 8; i < 16; ++i) {
            int e = t + i * 256;
            cp_async16(base + e * 16, g + e);
        }
        cp_async_commit();
    }

    fSt[(t & 31) * 8 + (t >> 5)] = g_feats[s0 * N_FILT + t];
    for (int i = t; i < HID * NCLS; i += 256) {
        int h = i / NCLS, c = i - h * NCLS;
        WlS[c * HID + h] = Wl[i];
    }
    __syncthreads();

    // ---- Layer 1 (32 -> 128) ----
    {
        float b = b1[hu];
        float a0 = b, a1 = b, a2 = b, a3 = b;
#pragma unroll
        for (int ff = 0; ff < N_FILT; ++ff) {
            float w = W1[ff * HID + hu];
            float4 v = *reinterpret_cast<const float4*>(&fSt[ff * 8 + half * 4]);
            a0 = fmaf(v.x, w, a0);
            a1 = fmaf(v.y, w, a1);
            a2 = fmaf(v.z, w, a2);
            a3 = fmaf(v.w, w, a3);
        }
        float4 r = make_float4(fmaxf(a0, 0.f), fmaxf(a1, 0.f),
                               fmaxf(a2, 0.f), fmaxf(a3, 0.f));
        *reinterpret_cast<float4*>(&t1S[hu * 8 + half * 4]) = r;
    }

    // ---- Layer 2 (128 -> 128), split on W2 halves ----
    float c0 = 0.f, c1 = 0.f, c2 = 0.f, c3 = 0.f;

    asm volatile("cp.async.wait_group 1;");   // lower half resident
    __syncthreads();                           // t1S + W2s[0..63] visible
#pragma unroll 16
    for (int h = 0; h < 64; ++h) {
        float w = W2s[h * HID + hu];
        float4 v = *reinterpret_cast<const float4*>(&t1S[h * 8 + half * 4]);
        c0 = fmaf(v.x, w, c0);
        c1 = fmaf(v.y, w, c1);
        c2 = fmaf(v.z, w, c2);
        c3 = fmaf(v.w, w, c3);
    }
    asm volatile("cp.async.wait_group 0;");   // upper half resident
    __syncthreads();
#pragma unroll 16
    for (int h = 64; h < HID; ++h) {
        float w = W2s[h * HID + hu];
        float4 v = *reinterpret_cast<const float4*>(&t1S[h * 8 + half * 4]);
        c0 = fmaf(v.x, w, c0);
        c1 = fmaf(v.y, w, c1);
        c2 = fmaf(v.z, w, c2);
        c3 = fmaf(v.w, w, c3);
    }
    {
        float b = b2[hu];
        float4 r = make_float4(fmaxf(c0 + b, 0.f), fmaxf(c1 + b, 0.f),
                               fmaxf(c2 + b, 0.f), fmaxf(c3 + b, 0.f));
        *reinterpret_cast<float4*>(&t2S[hu * 8 + half * 4]) = r;
    }
    __syncthreads();

    // ---- Logits + softmax: warp w handles sequence s0 + w ----
    const int wid  = t >> 5;
    const int lane = t & 31;
    float acc[NCLS];
#pragma unroll
    for (int c = 0; c < NCLS; ++c) acc[c] = 0.f;
#pragma unroll
    for (int q = 0; q < 4; ++q) {
        int h = lane + q * 32;
        float v = t2S[h * 8 + wid];
#pragma unroll
        for (int c = 0; c < NCLS; ++c) acc[c] = fmaf(v, WlS[c * HID + h], acc[c]);
    }
#pragma unroll
    for (int off = 16; off > 0; off >>= 1) {
#pragma unroll
        for (int c = 0; c < NCLS; ++c)
            acc[c] += __shfl_xor_sync(0xffffffffu, acc[c], off);
    }
    if (lane == 0) {
        float mx = -__int_as_float(0x7f800000);
#pragma unroll
        for (int c = 0; c < NCLS; ++c) {
            acc[c] += bl[c];
            mx = fmaxf(mx, acc[c]);
        }
        float e[NCLS];
        float sum = 0.f;
#pragma unroll
        for (int c = 0; c < NCLS; ++c) {
            e[c] = __expf(acc[c] - mx);
            sum += e[c];
        }
        float inv = 1.f / sum;
#pragma unroll
        for (int c = 0; c < NCLS; ++c)
            out[(s0 + wid) * NCLS + c] = e[c] * inv;
    }
}

#define MLP_SMEM ((HID * HID + HID * 8 + HID * 8 + N_FILT * 8 + HID * NCLS) * 4)

extern "C" void kernel_launch(void* const* d_in, const int* in_sizes, int n_in,
                              void* d_out, int out_size) {
    const float* x       = (const float*)d_in[0];
    const float* kernels = (const float*)d_in[1];
    const float* W1      = (const float*)d_in[2];
    const float* b1      = (const float*)d_in[3];
    const float* W2      = (const float*)d_in[4];
    const float* b2      = (const float*)d_in[5];
    const float* Wl      = (const float*)d_in[6];
    const float* bl      = (const float*)d_in[7];
    float* out = (float*)d_out;

    cudaFuncSetAttribute(mlp_kernel, cudaFuncAttributeMaxDynamicSharedMemorySize, MLP_SMEM);

    dtw_kernel<<<N_SEQ / 2, 64>>>(x, kernels);
    mlp_kernel<<<N_SEQ / 8, 256, MLP_SMEM>>>(W1, b1, W2, b2, Wl, bl, out);
}

// round 10
// speedup vs baseline: 1.3683x; 1.3683x over previous
#include <cuda_runtime.h>
#include <math.h>
#include <stdint.h>

#define N_SEQ   2048
#define SEQ_LEN 24
#define SEQ_C   9
#define N_FILT  32
#define KM      16
#define HID     128
#define NCLS    10

#define MLP_SEQS 16   // sequences per MLP block -> 128 blocks = single wave

__device__ float g_kT[KM * SEQ_C * N_FILT];   // kernels transposed: [i][c][f]
__device__ float g_knorm[KM * N_FILT];        // |kernel row|^2:    [i][f]
__device__ float g_feats[N_SEQ * N_FILT];     // DTW features

__device__ __forceinline__ void cp_async16(uint32_t saddr, const void* gptr) {
    asm volatile("cp.async.cg.shared.global [%0], [%1], 16;" :: "r"(saddr), "l"(gptr));
}
__device__ __forceinline__ void cp_async_commit() {
    asm volatile("cp.async.commit_group;");
}
__device__ __forceinline__ void cp_async_wait_all() {
    asm volatile("cp.async.wait_group 0;");
}

// ---------------------------------------------------------------------------
// Kernel 1: transpose kernels to [i][c][f] + row norms. (r2 verbatim, FROZEN)
// ---------------------------------------------------------------------------
__global__ void prep_kernel(const float* __restrict__ kernels) {
    int idx = blockIdx.x * blockDim.x + threadIdx.x;
    if (idx >= KM * N_FILT) return;
    int i = idx >> 5;
    int f = idx & 31;
    float nrm = 0.f;
#pragma unroll
    for (int c = 0; c < SEQ_C; ++c) {
        float v = kernels[f * (KM * SEQ_C) + i * SEQ_C + c];
        g_kT[(i * SEQ_C + c) * N_FILT + f] = v;
        nrm = fmaf(v, v, nrm);
    }
    g_knorm[i * N_FILT + f] = nrm;
}

// ---------------------------------------------------------------------------
// Kernel 2: DTW forward DP. One warp per block/sequence, lane = filter.
// (r2 verbatim, FROZEN — measured-fastest structure across 4 alternatives)
// ---------------------------------------------------------------------------
__global__ __launch_bounds__(32) void dtw_kernel(const float* __restrict__ x) {
    __shared__ float seqS[SEQ_LEN * SEQ_C];
    __shared__ float snormS[SEQ_LEN];

    const int s = blockIdx.x;
    const int f = threadIdx.x;

    const float* xs = x + s * (SEQ_LEN * SEQ_C);
    for (int t = f; t < SEQ_LEN * SEQ_C; t += 32) seqS[t] = xs[t];
    __syncthreads();

    if (f < SEQ_LEN) {
        float a = 0.f;
#pragma unroll
        for (int c = 0; c < SEQ_C; ++c) {
            float v = seqS[f * SEQ_C + c];
            a = fmaf(v, v, a);
        }
        snormS[f] = a;
    }
    __syncthreads();

    float Dp[SEQ_LEN];

    {
        float k0[SEQ_C];
#pragma unroll
        for (int c = 0; c < SEQ_C; ++c) k0[c] = g_kT[c * N_FILT + f];
        float kn = g_knorm[f];
        float run = 0.f;
#pragma unroll
        for (int j = 0; j < SEQ_LEN; ++j) {
            float dot = 0.f;
#pragma unroll
            for (int c = 0; c < SEQ_C; ++c) dot = fmaf(k0[c], seqS[j * SEQ_C + c], dot);
            float Cv = fmaf(-2.f, dot, kn + snormS[j]);
            run = (j == 0) ? Cv : (run + Cv);
            Dp[j] = run;
        }
    }

    const float INF = __int_as_float(0x7f800000);

    for (int sw = 0; sw < 3; ++sw) {
        const int i0 = 1 + sw * 5;
        float kr[5][SEQ_C], knr[5], left[5];
#pragma unroll
        for (int r = 0; r < 5; ++r) {
#pragma unroll
            for (int c = 0; c < SEQ_C; ++c)
                kr[r][c] = g_kT[((i0 + r) * SEQ_C + c) * N_FILT + f];
            knr[r] = g_knorm[(i0 + r) * N_FILT + f];
            left[r] = INF;
        }
        float diagc = INF;
#pragma unroll
        for (int j = 0; j < SEQ_LEN; ++j) {
            float sv[SEQ_C];
#pragma unroll
            for (int c = 0; c < SEQ_C; ++c) sv[c] = seqS[j * SEQ_C + c];
            float sn = snormS[j];
            float up = Dp[j];
            float oldup = up;
            float diag = diagc;
#pragma unroll
            for (int r = 0; r < 5; ++r) {
                float dot = 0.f;
#pragma unroll
                for (int c = 0; c < SEQ_C; ++c) dot = fmaf(kr[r][c], sv[c], dot);
                float Cv = fmaf(-2.f, dot, knr[r] + sn);
                float best = fminf(left[r], fminf(up, diag));
                float d = Cv + best;
                diag = left[r];
                left[r] = d;
                up = d;
            }
            Dp[j] = up;
            diagc = oldup;
        }
    }

    g_feats[s * N_FILT + f] = Dp[SEQ_LEN - 1];
}

// ---------------------------------------------------------------------------
// Kernel 3: MLP, 16 seqs/block -> 128 blocks = ONE wave on 148 SMs.
// Thread = (hu = t&127, half = t>>7 -> which 8 sequences). W2 cp.async into
// smem overlapped with staging + layer 1 (r6-proven single wait). 8 FMA per
// W2 shared load. Logits: warp w handles sequences 2w, 2w+1.
// ---------------------------------------------------------------------------
__global__ __launch_bounds__(256) void mlp_kernel(
    const float* __restrict__ W1, const float* __restrict__ b1,
    const float* __restrict__ W2, const float* __restrict__ b2,
    const float* __restrict__ Wl, const float* __restrict__ bl,
    float* __restrict__ out) {
    extern __shared__ float smem[];
    float* W2s = smem;                        // [128*128]          64KB
    float* t1S = W2s + HID * HID;             // [h][16]             8KB
    float* t2S = t1S + HID * MLP_SEQS;        // [h][16]             8KB
    float* fSt = t2S + HID * MLP_SEQS;        // [filter][16]        2KB
    float* WlS = fSt + N_FILT * MLP_SEQS;     // [c][h] transposed   5KB

    const int t    = threadIdx.x;
    const int hu   = t & 127;
    const int half = t >> 7;                  // 0 -> seqs 0..7, 1 -> 8..15
    const int s0   = blockIdx.x * MLP_SEQS;

    // Prefetch W2 (64KB) via cp.async, single commit group.
    {
        uint32_t base = (uint32_t)__cvta_generic_to_shared(W2s);
        const float4* g = reinterpret_cast<const float4*>(W2);
#pragma unroll
        for (int i = 0; i < 16; ++i) {
            int e = t + i * 256;
            cp_async16(base + e * 16, g + e);
        }
        cp_async_commit();
    }

    // Stage features transposed [filter][seq] (coalesced reads) + Wl transposed.
#pragma unroll
    for (int i = t; i < N_FILT * MLP_SEQS; i += 256) {
        int sq = i >> 5, ff = i & 31;
        fSt[ff * MLP_SEQS + sq] = g_feats[s0 * N_FILT + i];
    }
    for (int i = t; i < HID * NCLS; i += 256) {
        int h = i / NCLS, c = i - h * NCLS;
        WlS[c * HID + h] = Wl[i];
    }
    __syncthreads();

    // ---- Layer 1 (32 -> 128): 8 seqs per thread ----
    {
        float b = b1[hu];
        float a0 = b, a1 = b, a2 = b, a3 = b, a4 = b, a5 = b, a6 = b, a7 = b;
#pragma unroll
        for (int ff = 0; ff < N_FILT; ++ff) {
            float w = W1[ff * HID + hu];
            const float4* p = reinterpret_cast<const float4*>(&fSt[ff * MLP_SEQS + half * 8]);
            float4 va = p[0], vb = p[1];
            a0 = fmaf(va.x, w, a0); a1 = fmaf(va.y, w, a1);
            a2 = fmaf(va.z, w, a2); a3 = fmaf(va.w, w, a3);
            a4 = fmaf(vb.x, w, a4); a5 = fmaf(vb.y, w, a5);
            a6 = fmaf(vb.z, w, a6); a7 = fmaf(vb.w, w, a7);
        }
        float4* q = reinterpret_cast<float4*>(&t1S[hu * MLP_SEQS + half * 8]);
        q[0] = make_float4(fmaxf(a0, 0.f), fmaxf(a1, 0.f), fmaxf(a2, 0.f), fmaxf(a3, 0.f));
        q[1] = make_float4(fmaxf(a4, 0.f), fmaxf(a5, 0.f), fmaxf(a6, 0.f), fmaxf(a7, 0.f));
    }
    cp_async_wait_all();
    __syncthreads();

    // ---- Layer 2 (128 -> 128): all smem, 8 FMA per W2 load ----
    {
        float c0 = 0.f, c1 = 0.f, c2 = 0.f, c3 = 0.f;
        float c4 = 0.f, c5 = 0.f, c6 = 0.f, c7 = 0.f;
#pragma unroll 16
        for (int h = 0; h < HID; ++h) {
            float w = W2s[h * HID + hu];
            const float4* p = reinterpret_cast<const float4*>(&t1S[h * MLP_SEQS + half * 8]);
            float4 va = p[0], vb = p[1];
            c0 = fmaf(va.x, w, c0); c1 = fmaf(va.y, w, c1);
            c2 = fmaf(va.z, w, c2); c3 = fmaf(va.w, w, c3);
            c4 = fmaf(vb.x, w, c4); c5 = fmaf(vb.y, w, c5);
            c6 = fmaf(vb.z, w, c6); c7 = fmaf(vb.w, w, c7);
        }
        float b = b2[hu];
        float4* q = reinterpret_cast<float4*>(&t2S[hu * MLP_SEQS + half * 8]);
        q[0] = make_float4(fmaxf(c0 + b, 0.f), fmaxf(c1 + b, 0.f),
                           fmaxf(c2 + b, 0.f), fmaxf(c3 + b, 0.f));
        q[1] = make_float4(fmaxf(c4 + b, 0.f), fmaxf(c5 + b, 0.f),
                           fmaxf(c6 + b, 0.f), fmaxf(c7 + b, 0.f));
    }
    __syncthreads();

    // ---- Logits + softmax: warp w handles sequences s0 + 2w, s0 + 2w + 1 ----
    const int wid  = t >> 5;
    const int lane = t & 31;
#pragma unroll
    for (int p = 0; p < 2; ++p) {
        const int sq = wid * 2 + p;
        float acc[NCLS];
#pragma unroll
        for (int c = 0; c < NCLS; ++c) acc[c] = 0.f;
#pragma unroll
        for (int q = 0; q < 4; ++q) {
            int h = lane + q * 32;
            float v = t2S[h * MLP_SEQS + sq];
#pragma unroll
            for (int c = 0; c < NCLS; ++c) acc[c] = fmaf(v, WlS[c * HID + h], acc[c]);
        }
#pragma unroll
        for (int off = 16; off > 0; off >>= 1) {
#pragma unroll
            for (int c = 0; c < NCLS; ++c)
                acc[c] += __shfl_xor_sync(0xffffffffu, acc[c], off);
        }
        if (lane == 0) {
            float mx = -__int_as_float(0x7f800000);
#pragma unroll
            for (int c = 0; c < NCLS; ++c) {
                acc[c] += bl[c];
                mx = fmaxf(mx, acc[c]);
            }
            float e[NCLS];
            float sum = 0.f;
#pragma unroll
            for (int c = 0; c < NCLS; ++c) {
                e[c] = __expf(acc[c] - mx);
                sum += e[c];
            }
            float inv = 1.f / sum;
#pragma unroll
            for (int c = 0; c < NCLS; ++c)
                out[(s0 + sq) * NCLS + c] = e[c] * inv;
        }
    }
}

#define MLP_SMEM ((HID * HID + HID * MLP_SEQS + HID * MLP_SEQS + N_FILT * MLP_SEQS + HID * NCLS) * 4)

extern "C" void kernel_launch(void* const* d_in, const int* in_sizes, int n_in,
                              void* d_out, int out_size) {
    const float* x       = (const float*)d_in[0];
    const float* kernels = (const float*)d_in[1];
    const float* W1      = (const float*)d_in[2];
    const float* b1      = (const float*)d_in[3];
    const float* W2      = (const float*)d_in[4];
    const float* b2      = (const float*)d_in[5];
    const float* Wl      = (const float*)d_in[6];
    const float* bl      = (const float*)d_in[7];
    float* out = (float*)d_out;

    cudaFuncSetAttribute(mlp_kernel, cudaFuncAttributeMaxDynamicSharedMemorySize, MLP_SMEM);

    prep_kernel<<<1, 512>>>(kernels);
    dtw_kernel<<<N_SEQ, 32>>>(x);
    mlp_kernel<<<N_SEQ / MLP_SEQS, 256, MLP_SMEM>>>(W1, b1, W2, b2, Wl, bl, out);
}